// round 10
// baseline (speedup 1.0000x reference)
#include <cuda_runtime.h>
#include <cuda_bf16.h>
#include <cstdint>

// out[t][o] = sum_h R[t][h] * W[o][h],  R = x @ basis^T, W = amp*cos(phase)
// Step 2 (R): mma.m16n8k8 TF32 single term over K=1024 (error ~2e-4).
// Step 3 (out): mma.m16n8k8 TF32, single term K=32; epilogue via
//               cp.async.bulk S2G (TMA path, bypasses L1 LSU wavefronts).
#define TOKENS 16384
#define INF    1024
#define HARM   32
#define OUTF   4096

// Scratch device globals
__device__ __align__(16) float g_R[TOKENS * HARM];   // 2 MB, tf32-rounded fp32
__device__ __align__(16) float g_W[OUTF * HARM];     // 512 KB, tf32-rounded fp32

__device__ __forceinline__ uint32_t smem_u32(const void* p) {
    uint32_t a;
    asm("{ .reg .u64 t; cvta.to.shared.u64 t, %1; cvt.u32.u64 %0, t; }"
        : "=r"(a) : "l"(p));
    return a;
}
__device__ __forceinline__ float tf32_rna(float v) {
    float r;
    asm("cvt.rna.tf32.f32 %0, %1;" : "=f"(r) : "f"(v));
    return r;
}
__device__ __forceinline__ uint32_t tf32_r(uint32_t v) {
    uint32_t r;
    asm("cvt.rna.tf32.f32 %0, %1;" : "=r"(r) : "r"(v));
    return r;
}

// ---------------------------------------------------------------------------
// Step 2 (+W prep): CTAs [0,256) compute R = x @ basis^T via TF32 mma.
// CTAs [256,288) compute W = tf32(amp*cos(phase)).  (unchanged from R9)
// ---------------------------------------------------------------------------
#define XPITCH 68
__global__ __launch_bounds__(128) void resonance_tf32_kernel(
    const float* __restrict__ x, const float* __restrict__ basis,
    const float* __restrict__ phase, const float* __restrict__ amp) {
    if (blockIdx.x >= 256) {
        int base = (blockIdx.x - 256) * 4096;
#pragma unroll
        for (int r = 0; r < 32; r++) {
            int idx = base + threadIdx.x + r * 128;
            g_W[idx] = tf32_rna(amp[idx] * cosf(phase[idx]));
        }
        return;
    }

    __shared__ float sx[64 * XPITCH];
    __shared__ float sb[32 * XPITCH];

    int tid  = threadIdx.x;
    int lane = tid & 31;
    int wid  = tid >> 5;
    int tb   = blockIdx.x * 64;

    uint32_t sx_b = smem_u32(sx), sb_b = smem_u32(sb);

    float acc[4][4];
#pragma unroll
    for (int j = 0; j < 4; j++)
#pragma unroll
        for (int c = 0; c < 4; c++) acc[j][c] = 0.0f;

    const float4* gx = reinterpret_cast<const float4*>(x);
    const float4* gb = reinterpret_cast<const float4*>(basis);

    float4 xp[8], bp[4];
#pragma unroll
    for (int r = 0; r < 8; r++) {
        int q = tid + r * 128;
        int row = q >> 4, c4 = q & 15;
        xp[r] = gx[(long)(tb + row) * (INF / 4) + c4];
    }
#pragma unroll
    for (int r = 0; r < 4; r++) {
        int q = tid + r * 128;
        int row = q >> 4, c4 = q & 15;
        bp[r] = gb[row * (INF / 4) + c4];
    }

    for (int ck = 0; ck < 16; ck++) {
        if (ck > 0) __syncthreads();
#pragma unroll
        for (int r = 0; r < 8; r++) {
            int q = tid + r * 128;
            int row = q >> 4, c4 = q & 15;
            *reinterpret_cast<float4*>(&sx[row * XPITCH + c4 * 4]) = xp[r];
        }
#pragma unroll
        for (int r = 0; r < 4; r++) {
            int q = tid + r * 128;
            int row = q >> 4, c4 = q & 15;
            *reinterpret_cast<float4*>(&sb[row * XPITCH + c4 * 4]) = bp[r];
        }
        __syncthreads();

        if (ck < 15) {
            int kc4 = (ck + 1) * 16;
#pragma unroll
            for (int r = 0; r < 8; r++) {
                int q = tid + r * 128;
                int row = q >> 4, c4 = q & 15;
                xp[r] = gx[(long)(tb + row) * (INF / 4) + kc4 + c4];
            }
#pragma unroll
            for (int r = 0; r < 4; r++) {
                int q = tid + r * 128;
                int row = q >> 4, c4 = q & 15;
                bp[r] = gb[row * (INF / 4) + kc4 + c4];
            }
        }

#pragma unroll
        for (int ks = 0; ks < 8; ks++) {
            uint32_t af[4];
            {
                int row = wid * 16 + (lane & 15);
                uint32_t ao = sx_b + (uint32_t)row * (XPITCH * 4) + ks * 32 + (lane >> 4) * 16;
                asm volatile(
                    "ldmatrix.sync.aligned.m8n8.x4.shared.b16 {%0,%1,%2,%3}, [%4];"
                    : "=r"(af[0]), "=r"(af[1]), "=r"(af[2]), "=r"(af[3])
                    : "r"(ao));
#pragma unroll
                for (int c = 0; c < 4; c++) af[c] = tf32_r(af[c]);
            }
#pragma unroll
            for (int j = 0; j < 4; j++) {
                int nrow = j * 8 + (lane & 7);
                uint32_t bo = sb_b + (uint32_t)nrow * (XPITCH * 4) + ks * 32 + ((lane >> 3) & 1) * 16;
                uint32_t bf[2];
                asm volatile(
                    "ldmatrix.sync.aligned.m8n8.x2.shared.b16 {%0,%1}, [%2];"
                    : "=r"(bf[0]), "=r"(bf[1]) : "r"(bo));
                bf[0] = tf32_r(bf[0]);
                bf[1] = tf32_r(bf[1]);
                asm volatile(
                    "mma.sync.aligned.m16n8k8.row.col.f32.tf32.tf32.f32 "
                    "{%0,%1,%2,%3}, {%4,%5,%6,%7}, {%8,%9}, {%0,%1,%2,%3};"
                    : "+f"(acc[j][0]), "+f"(acc[j][1]), "+f"(acc[j][2]), "+f"(acc[j][3])
                    : "r"(af[0]), "r"(af[1]), "r"(af[2]), "r"(af[3]),
                      "r"(bf[0]), "r"(bf[1]));
            }
        }
    }

    int qrow = lane >> 2;
    int qcol = (lane & 3) * 2;
#pragma unroll
    for (int j = 0; j < 4; j++) {
#pragma unroll
        for (int hh = 0; hh < 2; hh++) {
            long t = tb + wid * 16 + qrow + hh * 8;
            float v0 = tf32_rna(acc[j][hh * 2 + 0]);
            float v1 = tf32_rna(acc[j][hh * 2 + 1]);
            *reinterpret_cast<float2*>(&g_R[t * HARM + j * 8 + qcol]) =
                make_float2(v0, v1);
        }
    }
}

// ---------------------------------------------------------------------------
// Step 3: out = R @ W^T via mma.m16n8k8 TF32, K=32 single term.
// CTA 128 tokens x 256 outputs (2 B-subtiles up-front).
// Epilogue: per-warp staged 16x32 tile -> cp.async.bulk S2G per 128B row
// (TMA path; no L1 LSU wavefronts for the read+store). Double-buffered.
// ---------------------------------------------------------------------------
#define TPITCH 36
#define TILE_BYTES (128 * TPITCH * 4)       // 18432
#define SM3_TOTAL (3 * TILE_BYTES)          // A + B0 + B1 = 55296
#define WSTRIDE 40
#define NBT 2

__global__ __launch_bounds__(256, 2) void holo_tf32_kernel(float* __restrict__ out) {
    extern __shared__ char smem[];
    __shared__ __align__(16) float wstage[8][2][16 * WSTRIDE];  // 40 KB static
    char* sA = smem;

    int tid  = threadIdx.x;
    int lane = tid & 31;
    int wid  = tid >> 5;
    int warp_m = wid >> 2;   // 0..1
    int warp_n = wid & 3;    // 0..3

    int ob0 = blockIdx.x * 256;
    int tb  = blockIdx.y * 128;

    const float4* gA = reinterpret_cast<const float4*>(&g_R[(long)tb * HARM]);
    const float4* gB = reinterpret_cast<const float4*>(&g_W[(long)ob0 * HARM]);

#pragma unroll
    for (int r = 0; r < 4; r++) {
        int q = tid + r * 256;        // 0..1023
        int row = q >> 3, ch = q & 7;
        uint32_t soff = (uint32_t)row * (TPITCH * 4) + ch * 16;
        *reinterpret_cast<float4*>(sA + soff) = gA[q];
        *reinterpret_cast<float4*>(sA + TILE_BYTES + soff) = gB[q];
        *reinterpret_cast<float4*>(sA + 2 * TILE_BYTES + soff) = gB[1024 + q];
    }
    __syncthreads();

    uint32_t sAb = smem_u32(sA);
    int qrow = lane >> 2;
    int qcol = (lane & 3) * 2;
    int ep = 0;   // epilogue tile counter (buffer parity + wait gating)

#pragma unroll
    for (int nb = 0; nb < NBT; nb++) {
        uint32_t sBb = sAb + TILE_BYTES + (uint32_t)nb * TILE_BYTES;

        float acc[4][4][4];
#pragma unroll
        for (int i = 0; i < 4; i++)
#pragma unroll
            for (int j = 0; j < 4; j++)
#pragma unroll
                for (int c = 0; c < 4; c++) acc[i][j][c] = 0.0f;

#pragma unroll
        for (int ks = 0; ks < 4; ks++) {
            uint32_t af[4][4];
#pragma unroll
            for (int i = 0; i < 4; i++) {
                int row = warp_m * 64 + i * 16 + (lane & 15);
                uint32_t addr = sAb + (uint32_t)row * (TPITCH * 4) + ks * 32 + (lane >> 4) * 16;
                asm volatile(
                    "ldmatrix.sync.aligned.m8n8.x4.shared.b16 {%0,%1,%2,%3}, [%4];"
                    : "=r"(af[i][0]), "=r"(af[i][1]), "=r"(af[i][2]), "=r"(af[i][3])
                    : "r"(addr));
            }
            uint32_t bf[4][2];
#pragma unroll
            for (int j = 0; j < 4; j++) {
                int orow = warp_n * 32 + j * 8 + (lane & 7);
                uint32_t addr = sBb + (uint32_t)orow * (TPITCH * 4) + ks * 32 + ((lane >> 3) & 1) * 16;
                asm volatile(
                    "ldmatrix.sync.aligned.m8n8.x2.shared.b16 {%0,%1}, [%2];"
                    : "=r"(bf[j][0]), "=r"(bf[j][1])
                    : "r"(addr));
            }
#pragma unroll
            for (int i = 0; i < 4; i++)
#pragma unroll
                for (int j = 0; j < 4; j++) {
                    asm volatile(
                        "mma.sync.aligned.m16n8k8.row.col.f32.tf32.tf32.f32 "
                        "{%0,%1,%2,%3}, {%4,%5,%6,%7}, {%8,%9}, {%0,%1,%2,%3};"
                        : "+f"(acc[i][j][0]), "+f"(acc[i][j][1]),
                          "+f"(acc[i][j][2]), "+f"(acc[i][j][3])
                        : "r"(af[i][0]), "r"(af[i][1]), "r"(af[i][2]), "r"(af[i][3]),
                          "r"(bf[j][0]), "r"(bf[j][1]));
                }
        }

        // Epilogue: stage 16x32 per warp -> TMA bulk store per 128B row.
#pragma unroll
        for (int i = 0; i < 4; i++) {
            float* wb = wstage[wid][ep & 1];
            // Free this buffer: TMA reads from 2 tiles ago must be done.
            if (ep >= 2 && lane < 16)
                asm volatile("cp.async.bulk.wait_group.read 1;" ::: "memory");
            __syncwarp();
#pragma unroll
            for (int j = 0; j < 4; j++) {
                *reinterpret_cast<float2*>(&wb[qrow * WSTRIDE + j * 8 + qcol]) =
                    make_float2(acc[i][j][0], acc[i][j][1]);
                *reinterpret_cast<float2*>(&wb[(qrow + 8) * WSTRIDE + j * 8 + qcol]) =
                    make_float2(acc[i][j][2], acc[i][j][3]);
            }
            __syncwarp();
            asm volatile("fence.proxy.async.shared::cta;" ::: "memory");
            if (lane < 16) {
                long r0 = tb + warp_m * 64 + i * 16 + lane;
                long c0 = ob0 + nb * 128 + warp_n * 32;
                uint32_t sa = smem_u32(&wb[lane * WSTRIDE]);
                asm volatile(
                    "cp.async.bulk.global.shared::cta.bulk_group [%0], [%1], 128;"
                    :: "l"(&out[r0 * OUTF + c0]), "r"(sa) : "memory");
                asm volatile("cp.async.bulk.commit_group;" ::: "memory");
            }
            ep++;
        }
    }

    // Drain all pending bulk stores before exit.
    if (lane < 16)
        asm volatile("cp.async.bulk.wait_group 0;" ::: "memory");
}

// ---------------------------------------------------------------------------
extern "C" void kernel_launch(void* const* d_in, const int* in_sizes, int n_in,
                              void* d_out, int out_size) {
    const float* x     = (const float*)d_in[0];  // [16384,1024]
    const float* basis = (const float*)d_in[1];  // [32,1024]
    const float* phase = (const float*)d_in[2];  // [4096,32]
    const float* amp   = (const float*)d_in[3];  // [4096,32]
    float* out = (float*)d_out;                  // [16384,4096]

    cudaFuncSetAttribute(holo_tf32_kernel,
                         cudaFuncAttributeMaxDynamicSharedMemorySize, SM3_TOTAL);

    resonance_tf32_kernel<<<256 + 32, 128>>>(x, basis, phase, amp);
    dim3 gridC(OUTF / 256, TOKENS / 128);
    holo_tf32_kernel<<<gridC, 256, SM3_TOTAL>>>(out);
}

// round 12
// speedup vs baseline: 1.1364x; 1.1364x over previous
#include <cuda_runtime.h>
#include <cuda_bf16.h>
#include <cstdint>

// out[t][o] = sum_h R[t][h] * W[o][h],  R = x @ basis^T, W = amp*cos(phase)
// Step 2 (R): mma.m16n8k8 TF32 single term over K=1024, cp.async 2-stage ring.
// Step 3 (out): mma.m16n8k8 TF32, single term K=32 (R9-proven, 53.3us).
// Combined error ~4e-4 < 1e-3.
#define TOKENS 16384
#define INF    1024
#define HARM   32
#define OUTF   4096

// Scratch device globals
__device__ __align__(16) float g_R[TOKENS * HARM];   // 2 MB, tf32-rounded fp32
__device__ __align__(16) float g_W[OUTF * HARM];     // 512 KB, tf32-rounded fp32

__device__ __forceinline__ uint32_t smem_u32(const void* p) {
    uint32_t a;
    asm("{ .reg .u64 t; cvta.to.shared.u64 t, %1; cvt.u32.u64 %0, t; }"
        : "=r"(a) : "l"(p));
    return a;
}
__device__ __forceinline__ float tf32_rna(float v) {
    float r;
    asm("cvt.rna.tf32.f32 %0, %1;" : "=f"(r) : "f"(v));
    return r;
}
__device__ __forceinline__ uint32_t tf32_r(uint32_t v) {
    uint32_t r;
    asm("cvt.rna.tf32.f32 %0, %1;" : "=r"(r) : "r"(v));
    return r;
}
#define CPA16(dst, src) \
    asm volatile("cp.async.cg.shared.global [%0], [%1], 16;" \
                 :: "r"(dst), "l"(src) : "memory")
#define CPA_COMMIT() asm volatile("cp.async.commit_group;" ::: "memory")
#define CPA_WAIT1()  asm volatile("cp.async.wait_group 1;" ::: "memory")
#define CPA_WAIT0()  asm volatile("cp.async.wait_group 0;" ::: "memory")

// ---------------------------------------------------------------------------
// Step 2 (+W prep): CTAs [0,256) compute R = x @ basis^T via TF32 mma with a
// 2-stage cp.async ring (no RF transit for tiles). CTAs [256,288) compute W.
// Tile: 64 tokens x 32 harmonics, K chunks of 64 fp32, pitch 68 floats.
// Tail fix vs R11: last iteration must wait_group 0 (only ONE group is
// pending at ck=15, so wait_group 1 would not guarantee completion).
// ---------------------------------------------------------------------------
#define XPITCH 68
#define SX_BYTES (64 * XPITCH * 4)    // 17408
#define SB_BYTES (32 * XPITCH * 4)    // 8704
#define SMR_TOTAL (2 * SX_BYTES + 2 * SB_BYTES)   // 52224

__global__ __launch_bounds__(128) void resonance_tf32_kernel(
    const float* __restrict__ x, const float* __restrict__ basis,
    const float* __restrict__ phase, const float* __restrict__ amp) {
    // ---- W-prep CTAs ----
    if (blockIdx.x >= 256) {
        int base = (blockIdx.x - 256) * 4096;
#pragma unroll
        for (int r = 0; r < 32; r++) {
            int idx = base + threadIdx.x + r * 128;
            g_W[idx] = tf32_rna(amp[idx] * cosf(phase[idx]));
        }
        return;
    }

    extern __shared__ char smem[];
    uint32_t sbase = smem_u32(smem);

    int tid  = threadIdx.x;
    int lane = tid & 31;
    int wid  = tid >> 5;
    int tb   = blockIdx.x * 64;

    auto issue_chunk = [&](int ck, int s) {
        uint32_t sx = sbase + (uint32_t)s * SX_BYTES;
        uint32_t sb = sbase + 2 * SX_BYTES + (uint32_t)s * SB_BYTES;
        const float* xsrc = x + (long)ck * 64;
        const float* bsrc = basis + ck * 64;
#pragma unroll
        for (int r = 0; r < 8; r++) {
            int q = tid + r * 128;
            int row = q >> 4, c4 = q & 15;
            CPA16(sx + (uint32_t)row * (XPITCH * 4) + c4 * 16,
                  xsrc + (long)(tb + row) * INF + c4 * 4);
        }
#pragma unroll
        for (int r = 0; r < 4; r++) {
            int q = tid + r * 128;
            int row = q >> 4, c4 = q & 15;
            CPA16(sb + (uint32_t)row * (XPITCH * 4) + c4 * 16,
                  bsrc + (long)row * INF + c4 * 4);
        }
        CPA_COMMIT();
    };

    float acc[4][4];
#pragma unroll
    for (int j = 0; j < 4; j++)
#pragma unroll
        for (int c = 0; c < 4; c++) acc[j][c] = 0.0f;

    issue_chunk(0, 0);
    issue_chunk(1, 1);

    for (int ck = 0; ck < 16; ck++) {
        int s = ck & 1;
        // Retire group ck. At ck=15 only one group is pending -> wait 0.
        if (ck < 15) CPA_WAIT1(); else CPA_WAIT0();
        __syncthreads();

        uint32_t sx_b = sbase + (uint32_t)s * SX_BYTES;
        uint32_t sb_b = sbase + 2 * SX_BYTES + (uint32_t)s * SB_BYTES;

#pragma unroll
        for (int ks = 0; ks < 8; ks++) {
            uint32_t af[4];
            {
                int row = wid * 16 + (lane & 15);
                uint32_t ao = sx_b + (uint32_t)row * (XPITCH * 4) + ks * 32 + (lane >> 4) * 16;
                asm volatile(
                    "ldmatrix.sync.aligned.m8n8.x4.shared.b16 {%0,%1,%2,%3}, [%4];"
                    : "=r"(af[0]), "=r"(af[1]), "=r"(af[2]), "=r"(af[3])
                    : "r"(ao));
#pragma unroll
                for (int c = 0; c < 4; c++) af[c] = tf32_r(af[c]);
            }
#pragma unroll
            for (int j = 0; j < 4; j++) {
                int nrow = j * 8 + (lane & 7);
                uint32_t bo = sb_b + (uint32_t)nrow * (XPITCH * 4) + ks * 32 + ((lane >> 3) & 1) * 16;
                uint32_t bf[2];
                asm volatile(
                    "ldmatrix.sync.aligned.m8n8.x2.shared.b16 {%0,%1}, [%2];"
                    : "=r"(bf[0]), "=r"(bf[1]) : "r"(bo));
                bf[0] = tf32_r(bf[0]);
                bf[1] = tf32_r(bf[1]);
                asm volatile(
                    "mma.sync.aligned.m16n8k8.row.col.f32.tf32.tf32.f32 "
                    "{%0,%1,%2,%3}, {%4,%5,%6,%7}, {%8,%9}, {%0,%1,%2,%3};"
                    : "+f"(acc[j][0]), "+f"(acc[j][1]), "+f"(acc[j][2]), "+f"(acc[j][3])
                    : "r"(af[0]), "r"(af[1]), "r"(af[2]), "r"(af[3]),
                      "r"(bf[0]), "r"(bf[1]));
            }
        }

        __syncthreads();       // all warps done with stage s
        if (ck + 2 < 16) issue_chunk(ck + 2, s);
    }

    // Epilogue: tf32-rounded fp32 R, coalesced float2 stores.
    int qrow = lane >> 2;
    int qcol = (lane & 3) * 2;
#pragma unroll
    for (int j = 0; j < 4; j++) {
#pragma unroll
        for (int hh = 0; hh < 2; hh++) {
            long t = tb + wid * 16 + qrow + hh * 8;
            float v0 = tf32_rna(acc[j][hh * 2 + 0]);
            float v1 = tf32_rna(acc[j][hh * 2 + 1]);
            *reinterpret_cast<float2*>(&g_R[t * HARM + j * 8 + qcol]) =
                make_float2(v0, v1);
        }
    }
}

// ---------------------------------------------------------------------------
// Step 3: out = R @ W^T via mma.m16n8k8 TF32, K=32 single term.
// CTA covers 128 tokens x 256 outputs (2 B-subtiles, loaded up-front).
// 8 warps = 2(m) x 4(n), warp tile 64x32 per subtile.
// Tiles 128 rows x 32 f32, pitch 36 f32. Staged epilogue -> __stcs STG.128.
// (R9 version verbatim — measured 53.3us)
// ---------------------------------------------------------------------------
#define TPITCH 36
#define TILE_BYTES (128 * TPITCH * 4)       // 18432
#define SM3_TOTAL (3 * TILE_BYTES)          // A + B0 + B1 = 55296
#define WSTRIDE 40
#define NBT 2

__global__ __launch_bounds__(256, 2) void holo_tf32_kernel(float* __restrict__ out) {
    extern __shared__ char smem[];
    __shared__ float wstage[8][16 * WSTRIDE];
    char* sA = smem;

    int tid  = threadIdx.x;
    int lane = tid & 31;
    int wid  = tid >> 5;
    int warp_m = wid >> 2;   // 0..1
    int warp_n = wid & 3;    // 0..3

    int ob0 = blockIdx.x * 256;
    int tb  = blockIdx.y * 128;

    const float4* gA = reinterpret_cast<const float4*>(&g_R[(long)tb * HARM]);
    const float4* gB = reinterpret_cast<const float4*>(&g_W[(long)ob0 * HARM]);

#pragma unroll
    for (int r = 0; r < 4; r++) {
        int q = tid + r * 256;        // 0..1023
        int row = q >> 3, ch = q & 7;
        uint32_t soff = (uint32_t)row * (TPITCH * 4) + ch * 16;
        *reinterpret_cast<float4*>(sA + soff) = gA[q];
        *reinterpret_cast<float4*>(sA + TILE_BYTES + soff) = gB[q];
        *reinterpret_cast<float4*>(sA + 2 * TILE_BYTES + soff) = gB[1024 + q];
    }
    __syncthreads();

    uint32_t sAb = smem_u32(sA);
    int qrow = lane >> 2;
    int qcol = (lane & 3) * 2;

#pragma unroll
    for (int nb = 0; nb < NBT; nb++) {
        uint32_t sBb = sAb + TILE_BYTES + (uint32_t)nb * TILE_BYTES;

        float acc[4][4][4];
#pragma unroll
        for (int i = 0; i < 4; i++)
#pragma unroll
            for (int j = 0; j < 4; j++)
#pragma unroll
                for (int c = 0; c < 4; c++) acc[i][j][c] = 0.0f;

#pragma unroll
        for (int ks = 0; ks < 4; ks++) {
            uint32_t af[4][4];
#pragma unroll
            for (int i = 0; i < 4; i++) {
                int row = warp_m * 64 + i * 16 + (lane & 15);
                uint32_t addr = sAb + (uint32_t)row * (TPITCH * 4) + ks * 32 + (lane >> 4) * 16;
                asm volatile(
                    "ldmatrix.sync.aligned.m8n8.x4.shared.b16 {%0,%1,%2,%3}, [%4];"
                    : "=r"(af[i][0]), "=r"(af[i][1]), "=r"(af[i][2]), "=r"(af[i][3])
                    : "r"(addr));
            }
            uint32_t bf[4][2];
#pragma unroll
            for (int j = 0; j < 4; j++) {
                int orow = warp_n * 32 + j * 8 + (lane & 7);
                uint32_t addr = sBb + (uint32_t)orow * (TPITCH * 4) + ks * 32 + ((lane >> 3) & 1) * 16;
                asm volatile(
                    "ldmatrix.sync.aligned.m8n8.x2.shared.b16 {%0,%1}, [%2];"
                    : "=r"(bf[j][0]), "=r"(bf[j][1])
                    : "r"(addr));
            }
#pragma unroll
            for (int i = 0; i < 4; i++)
#pragma unroll
                for (int j = 0; j < 4; j++) {
                    asm volatile(
                        "mma.sync.aligned.m16n8k8.row.col.f32.tf32.tf32.f32 "
                        "{%0,%1,%2,%3}, {%4,%5,%6,%7}, {%8,%9}, {%0,%1,%2,%3};"
                        : "+f"(acc[i][j][0]), "+f"(acc[i][j][1]),
                          "+f"(acc[i][j][2]), "+f"(acc[i][j][3])
                        : "r"(af[i][0]), "r"(af[i][1]), "r"(af[i][2]), "r"(af[i][3]),
                          "r"(bf[j][0]), "r"(bf[j][1]));
                }
        }

        float* wb = wstage[wid];
#pragma unroll
        for (int i = 0; i < 4; i++) {
#pragma unroll
            for (int j = 0; j < 4; j++) {
                *reinterpret_cast<float2*>(&wb[qrow * WSTRIDE + j * 8 + qcol]) =
                    make_float2(acc[i][j][0], acc[i][j][1]);
                *reinterpret_cast<float2*>(&wb[(qrow + 8) * WSTRIDE + j * 8 + qcol]) =
                    make_float2(acc[i][j][2], acc[i][j][3]);
            }
            __syncwarp();
            long r0 = tb + warp_m * 64 + i * 16;
            long c0 = ob0 + nb * 128 + warp_n * 32;
#pragma unroll
            for (int s = 0; s < 4; s++) {
                int q = lane + s * 32;
                int row = q >> 3, c4 = q & 7;
                float4 v = *reinterpret_cast<float4*>(&wb[row * WSTRIDE + c4 * 4]);
                __stcs(reinterpret_cast<float4*>(&out[(r0 + row) * OUTF + c0 + c4 * 4]), v);
            }
            __syncwarp();
        }
    }
}

// ---------------------------------------------------------------------------
extern "C" void kernel_launch(void* const* d_in, const int* in_sizes, int n_in,
                              void* d_out, int out_size) {
    const float* x     = (const float*)d_in[0];  // [16384,1024]
    const float* basis = (const float*)d_in[1];  // [32,1024]
    const float* phase = (const float*)d_in[2];  // [4096,32]
    const float* amp   = (const float*)d_in[3];  // [4096,32]
    float* out = (float*)d_out;                  // [16384,4096]

    cudaFuncSetAttribute(resonance_tf32_kernel,
                         cudaFuncAttributeMaxDynamicSharedMemorySize, SMR_TOTAL);
    cudaFuncSetAttribute(holo_tf32_kernel,
                         cudaFuncAttributeMaxDynamicSharedMemorySize, SM3_TOTAL);

    resonance_tf32_kernel<<<256 + 32, 128, SMR_TOTAL>>>(x, basis, phase, amp);
    dim3 gridC(OUTF / 256, TOKENS / 128);
    holo_tf32_kernel<<<gridC, 256, SM3_TOTAL>>>(out);
}